// round 9
// baseline (speedup 1.0000x reference)
#include <cuda_runtime.h>
#include <cuda_fp16.h>
#include <cstdint>

// Problem constants (fixed by reference):
//   bsv=1, nq=nv=1024, E=128, NUM_DEPTH=128, NUM_POINTS=4, H=W=32, cams=heads=levels=1
// Inputs (metadata order):
//   0 query[1024,128] 1 key[1024,128] 2 value[1024,128] 3 ref_3d[131072,2]
//   4 spatial_shapes[1,2] 5 W_off[128,1024] 6 b_off[1024] 7 W_attn[128,512]
//   8 b_attn[512] 9 W_v[128,128] 10 b_v[128] 11 W_o[128,128] 12 b_o[128]
// Output: float32 [1024,128]
//
// Algebra: S = key @ (value@W_v + b_v)^T = (key@W_v^T) @ value^T + c,
//          c[i] = key[i]·b_v.
// ONE persistent kernel; grid-wide ticket barriers between the 4 stages
// (launch-count-independent: monotonic 64-bit counters, no reset needed).

#define NQ 1024
#define NV 1024
#define ND 128
#define TPB 128

// Scratch (allocation-free: __device__ globals)
__device__ float  g_kv[NQ * 128];
__device__ float  g_c[NQ];
__device__ __half g_S[NQ * NV];
__device__ __half g_off[NQ * 1024];
__device__ __half g_aw[NQ * 512];
__device__ float  g_M[NQ * ND];
__device__ unsigned long long g_bar[3];   // ticket counters (never reset)

// ---------------------------------------------------------------------------
__device__ __forceinline__ uint32_t f2tf32(float f) {
    uint32_t u;
    asm("cvt.rna.tf32.f32 %0, %1;" : "=r"(u) : "f"(f));
    return u;
}

__device__ __forceinline__ void mma_tf32(float c[4], const uint32_t a[4],
                                         const uint32_t b[2]) {
    asm volatile(
        "mma.sync.aligned.m16n8k8.row.col.f32.tf32.tf32.f32 "
        "{%0,%1,%2,%3}, {%4,%5,%6,%7}, {%8,%9}, {%0,%1,%2,%3};"
        : "+f"(c[0]), "+f"(c[1]), "+f"(c[2]), "+f"(c[3])
        : "r"(a[0]), "r"(a[1]), "r"(a[2]), "r"(a[3]), "r"(b[0]), "r"(b[1]));
}

// Grid-wide barrier: monotonic ticket. Works for any number of launches.
__device__ __forceinline__ void grid_barrier(int i) {
    __syncthreads();
    if (threadIdx.x == 0) {
        __threadfence();
        unsigned long long t = atomicAdd(&g_bar[i], 1ULL);
        unsigned long long target = (t / gridDim.x + 1ULL) * gridDim.x;
        while (atomicAdd(&g_bar[i], 0ULL) < target) __nanosleep(64);
        __threadfence();
    }
    __syncthreads();
}

// ---------------------------------------------------------------------------
// tf32 GEMM core (R7-proven LDG staging: tf32 conversion at stage time).
// BM=BN=64, 128 threads (4 warps, 2x2 warp grid, 32x32 warp tiles), full K=128.
// NT: B is [N,128] (A @ B^T); else B is [128,N] row-major.
// ---------------------------------------------------------------------------
#define ASZ (64 * 132)
#define BSZ (128 * 72)
#define GEMM_SMEM ((ASZ + BSZ) * 4)

template <bool NT, bool HAS_BIAS, bool HAS_ROWB, bool OUT_HALF>
__device__ __forceinline__ void gemm_core(
    const float* __restrict__ A, const float* __restrict__ B,
    const float* __restrict__ bias, const float* __restrict__ rowb,
    void* __restrict__ Cv, int N, int bm, int bn, uint32_t* sm)
{
    uint32_t* As = sm;
    uint32_t* Bs = sm + ASZ;

    const int tid  = threadIdx.x;
    const int lane = tid & 31;
    const int warp = tid >> 5;
    const int wm   = warp >> 1;
    const int wn   = warp & 1;
    const int grp  = lane >> 2;
    const int lk   = lane & 3;

    __syncthreads();   // smem reuse across sequential tiles

#pragma unroll
    for (int l = 0; l < 16; l++) {
        int f = tid + l * 128;
        int m = f >> 5, k4 = f & 31;
        float4 v = *reinterpret_cast<const float4*>(A + (bm + m) * 128 + k4 * 4);
        uint32_t* d = &As[m * 132 + k4 * 4];
        d[0] = f2tf32(v.x); d[1] = f2tf32(v.y);
        d[2] = f2tf32(v.z); d[3] = f2tf32(v.w);
    }
    if (NT) {
#pragma unroll
        for (int l = 0; l < 16; l++) {
            int f = tid + l * 128;
            int n = f >> 5, k4 = f & 31;
            float4 v = *reinterpret_cast<const float4*>(B + (bn + n) * 128 + k4 * 4);
            uint32_t* d = &Bs[n * 132 + k4 * 4];
            d[0] = f2tf32(v.x); d[1] = f2tf32(v.y);
            d[2] = f2tf32(v.z); d[3] = f2tf32(v.w);
        }
    } else {
#pragma unroll
        for (int l = 0; l < 16; l++) {
            int f = tid + l * 128;
            int k = f >> 4, n4 = f & 15;
            float4 v = *reinterpret_cast<const float4*>(B + k * N + bn + n4 * 4);
            uint32_t* d = &Bs[k * 72 + n4 * 4];
            d[0] = f2tf32(v.x); d[1] = f2tf32(v.y);
            d[2] = f2tf32(v.z); d[3] = f2tf32(v.w);
        }
    }
    __syncthreads();

    float acc[2][4][4];
#pragma unroll
    for (int mi = 0; mi < 2; mi++)
#pragma unroll
        for (int ni = 0; ni < 4; ni++)
#pragma unroll
            for (int r = 0; r < 4; r++) acc[mi][ni][r] = 0.0f;

#pragma unroll
    for (int k8 = 0; k8 < 16; k8++) {
        const int kb = k8 * 8;
        uint32_t a[2][4], b[4][2];
#pragma unroll
        for (int mi = 0; mi < 2; mi++) {
            int mr = wm * 32 + mi * 16 + grp;
            a[mi][0] = As[mr * 132 + kb + lk];
            a[mi][1] = As[(mr + 8) * 132 + kb + lk];
            a[mi][2] = As[mr * 132 + kb + lk + 4];
            a[mi][3] = As[(mr + 8) * 132 + kb + lk + 4];
        }
#pragma unroll
        for (int ni = 0; ni < 4; ni++) {
            int nc = wn * 32 + ni * 8 + grp;
            if (NT) {
                b[ni][0] = Bs[nc * 132 + kb + lk];
                b[ni][1] = Bs[nc * 132 + kb + lk + 4];
            } else {
                b[ni][0] = Bs[(kb + lk) * 72 + nc];
                b[ni][1] = Bs[(kb + lk + 4) * 72 + nc];
            }
        }
#pragma unroll
        for (int mi = 0; mi < 2; mi++)
#pragma unroll
            for (int ni = 0; ni < 4; ni++)
                mma_tf32(acc[mi][ni], a[mi], b[ni]);
    }

#pragma unroll
    for (int mi = 0; mi < 2; mi++) {
#pragma unroll
        for (int h = 0; h < 2; h++) {
            int row = bm + wm * 32 + mi * 16 + grp + h * 8;
            float rb = HAS_ROWB ? rowb[row] : 0.0f;
#pragma unroll
            for (int ni = 0; ni < 4; ni++) {
                int col = bn + wn * 32 + ni * 8 + 2 * lk;
                float vx = acc[mi][ni][h * 2 + 0] + rb;
                float vy = acc[mi][ni][h * 2 + 1] + rb;
                if (HAS_BIAS) { vx += bias[col]; vy += bias[col + 1]; }
                if (OUT_HALF) {
                    *reinterpret_cast<__half2*>(
                        (__half*)Cv + (size_t)row * N + col) =
                        __floats2half2_rn(vx, vy);
                } else {
                    float2 v2; v2.x = vx; v2.y = vy;
                    *reinterpret_cast<float2*>(
                        (float*)Cv + (size_t)row * N + col) = v2;
                }
            }
        }
    }
}

// Out-proj strip tile: BM=16, BN=64, warp tile 16x16.
__device__ __forceinline__ void out_tile(
    const float* __restrict__ M, const float* __restrict__ Wo,
    const float* __restrict__ bo, const float* __restrict__ query,
    float* __restrict__ out, int bm, int bn, uint32_t* sm)
{
    uint32_t* As = sm;            // 16 x 132
    uint32_t* Bs = sm + 16 * 132; // 128 x 72

    const int tid  = threadIdx.x;
    const int lane = tid & 31;
    const int warp = tid >> 5;
    const int grp  = lane >> 2;
    const int lk   = lane & 3;

    __syncthreads();
#pragma unroll
    for (int l = 0; l < 4; l++) {
        int f = tid + l * 128;
        int m = f >> 5, k4 = f & 31;
        float4 v = *reinterpret_cast<const float4*>(M + (bm + m) * 128 + k4 * 4);
        uint32_t* d = &As[m * 132 + k4 * 4];
        d[0] = f2tf32(v.x); d[1] = f2tf32(v.y);
        d[2] = f2tf32(v.z); d[3] = f2tf32(v.w);
    }
#pragma unroll
    for (int l = 0; l < 16; l++) {
        int f = tid + l * 128;
        int k = f >> 4, n4 = f & 15;
        float4 v = *reinterpret_cast<const float4*>(Wo + k * 128 + bn + n4 * 4);
        uint32_t* d = &Bs[k * 72 + n4 * 4];
        d[0] = f2tf32(v.x); d[1] = f2tf32(v.y);
        d[2] = f2tf32(v.z); d[3] = f2tf32(v.w);
    }
    __syncthreads();

    float acc[2][4];
#pragma unroll
    for (int ni = 0; ni < 2; ni++)
#pragma unroll
        for (int r = 0; r < 4; r++) acc[ni][r] = 0.0f;

#pragma unroll
    for (int k8 = 0; k8 < 16; k8++) {
        const int kb = k8 * 8;
        uint32_t a[4], b[2][2];
        a[0] = As[grp * 132 + kb + lk];
        a[1] = As[(grp + 8) * 132 + kb + lk];
        a[2] = As[grp * 132 + kb + lk + 4];
        a[3] = As[(grp + 8) * 132 + kb + lk + 4];
#pragma unroll
        for (int ni = 0; ni < 2; ni++) {
            int nc = warp * 16 + ni * 8 + grp;
            b[ni][0] = Bs[(kb + lk) * 72 + nc];
            b[ni][1] = Bs[(kb + lk + 4) * 72 + nc];
        }
#pragma unroll
        for (int ni = 0; ni < 2; ni++)
            mma_tf32(acc[ni], a, b[ni]);
    }

#pragma unroll
    for (int ni = 0; ni < 2; ni++) {
#pragma unroll
        for (int h = 0; h < 2; h++) {
            int row = bm + grp + h * 8;
            int col = bn + warp * 16 + ni * 8 + 2 * lk;
            float2 r = *reinterpret_cast<const float2*>(query + row * 128 + col);
            float2 v;
            v.x = acc[ni][h * 2 + 0] + bo[col] + r.x;
            v.y = acc[ni][h * 2 + 1] + bo[col + 1] + r.y;
            *reinterpret_cast<float2*>(out + row * 128 + col) = v;
        }
    }
}

// Sampler for one query row: 128 threads, thread d handles all 4 points.
__device__ __forceinline__ void sample_row(
    int q, const __half* __restrict__ S, const __half* __restrict__ off,
    const __half* __restrict__ aw, const float* __restrict__ ref3d,
    float* __restrict__ M, uint32_t* sm)
{
    __half* srow = reinterpret_cast<__half*>(sm);
    const int d = threadIdx.x;

    __syncthreads();   // srow reuse across q iterations
    // 1024 halves = 128 x uint4
    reinterpret_cast<uint4*>(srow)[d] =
        reinterpret_cast<const uint4*>(S + (size_t)q * NV)[d];

    const __half2* awp = reinterpret_cast<const __half2*>(aw + q * 512 + d * 4);
    float2 a01 = __half22float2(awp[0]);
    float2 a23 = __half22float2(awp[1]);
    float mx = fmaxf(fmaxf(a01.x, a01.y), fmaxf(a23.x, a23.y));
    float e0 = __expf(a01.x - mx), e1 = __expf(a01.y - mx);
    float e2 = __expf(a23.x - mx), e3 = __expf(a23.y - mx);
    float inv = 1.0f / (e0 + e1 + e2 + e3);
    float wp[4] = { e0 * inv, e1 * inv, e2 * inv, e3 * inv };

    const int qe = q * ND + d;
    const float2 rf = *reinterpret_cast<const float2*>(ref3d + qe * 2);
    const float rx = rf.x * 32.0f - 0.5f;
    const float ry = rf.y * 32.0f - 0.5f;

    const __half2* op = reinterpret_cast<const __half2*>(off + q * 1024 + d * 8);
    float2 p0 = __half22float2(op[0]);
    float2 p1 = __half22float2(op[1]);
    float2 p2 = __half22float2(op[2]);
    float2 p3 = __half22float2(op[3]);
    float ox[4] = { p0.x, p1.x, p2.x, p3.x };
    float oy[4] = { p0.y, p1.y, p2.y, p3.y };

    __syncthreads();

    float acc = 0.0f;
#pragma unroll
    for (int p = 0; p < 4; p++) {
        float x = rx + ox[p];
        float y = ry + oy[p];
        float xf = floorf(x), yf = floorf(y);
        int ix0 = (int)xf, iy0 = (int)yf;
        float wx1 = x - xf, wy1 = y - yf;
        float wx0 = 1.0f - wx1, wy0 = 1.0f - wy1;

        float s = 0.0f;
#pragma unroll
        for (int cc = 0; cc < 4; cc++) {
            int cx = ix0 + (cc & 1);
            int cy = iy0 + (cc >> 1);
            float wt = ((cc & 1) ? wx1 : wx0) * ((cc >> 1) ? wy1 : wy0);
            if (cx >= 0 && cx < 32 && cy >= 0 && cy < 32)
                s += wt * __half2float(srow[cy * 32 + cx]);
        }
        acc += wp[p] * s;
    }
    M[qe] = acc * (1.0f / 128.0f);
}

// ---------------------------------------------------------------------------
// The persistent mega-kernel: all 4 stages with grid barriers between.
// ---------------------------------------------------------------------------
__global__ __launch_bounds__(TPB)
void mega_kernel(const float* __restrict__ query, const float* __restrict__ key,
                 const float* __restrict__ value, const float* __restrict__ ref3d,
                 const float* __restrict__ Woff, const float* __restrict__ boff,
                 const float* __restrict__ Wattn, const float* __restrict__ battn,
                 const float* __restrict__ Wv, const float* __restrict__ bv,
                 const float* __restrict__ Wo, const float* __restrict__ bo,
                 float* __restrict__ out)
{
    extern __shared__ uint32_t sm[];

    // ---- Stage A: 416 tiles (off 16x16, aw 8x16, kv 2x16 incl. c vector)
    for (int t = blockIdx.x; t < 416; t += gridDim.x) {
        int bx = t % 26, by = t / 26;
        int bm = by * 64;
        if (bx < 16) {
            gemm_core<false, true, false, true>(
                query, Woff, boff, nullptr, g_off, 1024, bm, bx * 64, sm);
        } else if (bx < 24) {
            gemm_core<false, true, false, true>(
                query, Wattn, battn, nullptr, g_aw, 512, bm, (bx - 16) * 64, sm);
        } else {
            gemm_core<true, false, false, false>(
                key, Wv, nullptr, nullptr, g_kv, 128, bm, (bx - 24) * 64, sm);
            if (bx == 24) {
                const int tid = threadIdx.x;
                if (tid < 64) {
                    float s = 0.0f;
#pragma unroll 16
                    for (int e = 0; e < 128; e++)
                        s = fmaf(__uint_as_float(sm[tid * 132 + e]), bv[e], s);
                    g_c[bm + tid] = s;
                }
            }
        }
    }
    grid_barrier(0);

    // ---- Stage B: S = kv @ value^T + c[row]  (256 tiles)
    for (int t = blockIdx.x; t < 256; t += gridDim.x) {
        int bx = t & 15, by = t >> 4;
        gemm_core<true, false, true, true>(
            g_kv, value, nullptr, g_c, g_S, 1024, by * 64, bx * 64, sm);
    }
    grid_barrier(1);

    // ---- Stage C: sampler, 1024 query rows
    for (int q = blockIdx.x; q < 1024; q += gridDim.x)
        sample_row(q, g_S, g_off, g_aw, ref3d, g_M, sm);
    grid_barrier(2);

    // ---- Stage D: out = M @ W_o + b_o + query  (128 strip tiles)
    for (int t = blockIdx.x; t < 128; t += gridDim.x)
        out_tile(g_M, Wo, bo, query, out, (t >> 1) * 16, (t & 1) * 64, sm);
}

// ---------------------------------------------------------------------------
extern "C" void kernel_launch(void* const* d_in, const int* in_sizes, int n_in,
                              void* d_out, int out_size)
{
    const float* query  = (const float*)d_in[0];
    const float* key    = (const float*)d_in[1];
    const float* value  = (const float*)d_in[2];
    const float* ref3d  = (const float*)d_in[3];
    // d_in[4] spatial_shapes: fixed [[32,32]], hardcoded
    const float* W_off  = (const float*)d_in[5];
    const float* b_off  = (const float*)d_in[6];
    const float* W_attn = (const float*)d_in[7];
    const float* b_attn = (const float*)d_in[8];
    const float* W_v    = (const float*)d_in[9];
    const float* b_v    = (const float*)d_in[10];
    const float* W_o    = (const float*)d_in[11];
    const float* b_o    = (const float*)d_in[12];
    float* out = (float*)d_out;

    // Grid sized for guaranteed co-residency (deadlock-free barriers).
    static int gsz = 0;
    if (gsz == 0) {
        cudaFuncSetAttribute(mega_kernel,
                             cudaFuncAttributeMaxDynamicSharedMemorySize,
                             GEMM_SMEM);
        int nb = 0, sms = 0;
        cudaOccupancyMaxActiveBlocksPerMultiprocessor(&nb, mega_kernel,
                                                      TPB, GEMM_SMEM);
        cudaDeviceGetAttribute(&sms, cudaDevAttrMultiProcessorCount, 0);
        if (nb < 1) nb = 1;
        gsz = nb * sms;
        if (gsz > 416) gsz = 416;   // no stage has more parallel work
        if (gsz < 1) gsz = 1;
    }

    mega_kernel<<<gsz, TPB, GEMM_SMEM>>>(
        query, key, value, ref3d, W_off, b_off, W_attn, b_attn,
        W_v, b_v, W_o, b_o, out);
}

// round 10
// speedup vs baseline: 1.0024x; 1.0024x over previous
#include <cuda_runtime.h>
#include <cuda_fp16.h>
#include <cstdint>

// Problem constants (fixed by reference):
//   bsv=1, nq=nv=1024, E=128, NUM_DEPTH=128, NUM_POINTS=4, H=W=32, cams=heads=levels=1
// Inputs (metadata order):
//   0 query[1024,128] 1 key[1024,128] 2 value[1024,128] 3 ref_3d[131072,2]
//   4 spatial_shapes[1,2] 5 W_off[128,1024] 6 b_off[1024] 7 W_attn[128,512]
//   8 b_attn[512] 9 W_v[128,128] 10 b_v[128] 11 W_o[128,128] 12 b_o[128]
// Output: float32 [1024,128]
//
// Algebra: S = key @ (value@W_v + b_v)^T = (key@W_v^T) @ value^T + c,
//          c[i] = key[i]·b_v.
// Dependency graph exploited:  off/aw = f(query) is independent of the
// kv -> S chain, so it runs concurrently on a side stream and joins only
// before the sampler.

#define NQ 1024
#define NV 1024
#define ND 128

// Scratch (allocation-free: __device__ globals)
__device__ float  g_kv[NQ * 128];      // key @ W_v^T                 (fp32)
__device__ float  g_c[NQ];             // key @ b_v  (row bias for S) (fp32)
__device__ __half g_S[NQ * NV];        // kv @ value^T + c            (fp16)
__device__ __half g_off[NQ * 1024];    // query @ W_off + b_off       (fp16)
__device__ __half g_aw[NQ * 512];      // query @ W_attn + b_attn     (fp16)
__device__ float  g_M[NQ * ND];        // sampled, pre-output-proj    (fp32)

// ---------------------------------------------------------------------------
// tf32 helpers
// ---------------------------------------------------------------------------
__device__ __forceinline__ uint32_t f2tf32(float f) {
    uint32_t u;
    asm("cvt.rna.tf32.f32 %0, %1;" : "=r"(u) : "f"(f));
    return u;
}

__device__ __forceinline__ void mma_tf32(float c[4], const uint32_t a[4],
                                         const uint32_t b[2]) {
    asm volatile(
        "mma.sync.aligned.m16n8k8.row.col.f32.tf32.tf32.f32 "
        "{%0,%1,%2,%3}, {%4,%5,%6,%7}, {%8,%9}, {%0,%1,%2,%3};"
        : "+f"(c[0]), "+f"(c[1]), "+f"(c[2]), "+f"(c[3])
        : "r"(a[0]), "r"(a[1]), "r"(a[2]), "r"(a[3]), "r"(b[0]), "r"(b[1]));
}

// ---------------------------------------------------------------------------
// tf32 GEMM core, FULL-K staging (K=128), tf32 cvt at stage time (R7-proven).
// BM=BN=64, 128 threads (4 warps, 2x2 warp grid, 32x32 warp tiles).
// NT: B is [N,128] (compute A @ B^T); else B is [128,N] row-major.
// Optional col bias[N], row bias rowb[M]. OUT_HALF: fp16 half2 stores.
// ---------------------------------------------------------------------------
#define ASZ (64 * 132)
#define BSZ (128 * 72)
#define GEMM_SMEM ((ASZ + BSZ) * 4)

template <bool NT, bool HAS_BIAS, bool HAS_ROWB, bool OUT_HALF>
__device__ __forceinline__ void gemm_core(
    const float* __restrict__ A, const float* __restrict__ B,
    const float* __restrict__ bias, const float* __restrict__ rowb,
    void* __restrict__ Cv, int N, int bm, int bn)
{
    extern __shared__ uint32_t sm[];
    uint32_t* As = sm;
    uint32_t* Bs = sm + ASZ;

    const int tid  = threadIdx.x;
    const int lane = tid & 31;
    const int warp = tid >> 5;
    const int wm   = warp >> 1;
    const int wn   = warp & 1;
    const int grp  = lane >> 2;
    const int lk   = lane & 3;

    // ---- stage A [64m x 128k]
#pragma unroll
    for (int l = 0; l < 16; l++) {
        int f = tid + l * 128;
        int m = f >> 5, k4 = f & 31;
        float4 v = *reinterpret_cast<const float4*>(A + (bm + m) * 128 + k4 * 4);
        uint32_t* d = &As[m * 132 + k4 * 4];
        d[0] = f2tf32(v.x); d[1] = f2tf32(v.y);
        d[2] = f2tf32(v.z); d[3] = f2tf32(v.w);
    }
    // ---- stage B
    if (NT) {
#pragma unroll
        for (int l = 0; l < 16; l++) {
            int f = tid + l * 128;
            int n = f >> 5, k4 = f & 31;
            float4 v = *reinterpret_cast<const float4*>(B + (bn + n) * 128 + k4 * 4);
            uint32_t* d = &Bs[n * 132 + k4 * 4];
            d[0] = f2tf32(v.x); d[1] = f2tf32(v.y);
            d[2] = f2tf32(v.z); d[3] = f2tf32(v.w);
        }
    } else {
#pragma unroll
        for (int l = 0; l < 16; l++) {
            int f = tid + l * 128;
            int k = f >> 4, n4 = f & 15;
            float4 v = *reinterpret_cast<const float4*>(B + k * N + bn + n4 * 4);
            uint32_t* d = &Bs[k * 72 + n4 * 4];
            d[0] = f2tf32(v.x); d[1] = f2tf32(v.y);
            d[2] = f2tf32(v.z); d[3] = f2tf32(v.w);
        }
    }
    __syncthreads();

    float acc[2][4][4];
#pragma unroll
    for (int mi = 0; mi < 2; mi++)
#pragma unroll
        for (int ni = 0; ni < 4; ni++)
#pragma unroll
            for (int r = 0; r < 4; r++) acc[mi][ni][r] = 0.0f;

#pragma unroll
    for (int k8 = 0; k8 < 16; k8++) {
        const int kb = k8 * 8;
        uint32_t a[2][4], b[4][2];
#pragma unroll
        for (int mi = 0; mi < 2; mi++) {
            int mr = wm * 32 + mi * 16 + grp;
            a[mi][0] = As[mr * 132 + kb + lk];
            a[mi][1] = As[(mr + 8) * 132 + kb + lk];
            a[mi][2] = As[mr * 132 + kb + lk + 4];
            a[mi][3] = As[(mr + 8) * 132 + kb + lk + 4];
        }
#pragma unroll
        for (int ni = 0; ni < 4; ni++) {
            int nc = wn * 32 + ni * 8 + grp;
            if (NT) {
                b[ni][0] = Bs[nc * 132 + kb + lk];
                b[ni][1] = Bs[nc * 132 + kb + lk + 4];
            } else {
                b[ni][0] = Bs[(kb + lk) * 72 + nc];
                b[ni][1] = Bs[(kb + lk + 4) * 72 + nc];
            }
        }
#pragma unroll
        for (int mi = 0; mi < 2; mi++)
#pragma unroll
            for (int ni = 0; ni < 4; ni++)
                mma_tf32(acc[mi][ni], a[mi], b[ni]);
    }

    // ---- epilogue
#pragma unroll
    for (int mi = 0; mi < 2; mi++) {
#pragma unroll
        for (int h = 0; h < 2; h++) {
            int row = bm + wm * 32 + mi * 16 + grp + h * 8;
            float rb = HAS_ROWB ? rowb[row] : 0.0f;
#pragma unroll
            for (int ni = 0; ni < 4; ni++) {
                int col = bn + wn * 32 + ni * 8 + 2 * lk;
                float vx = acc[mi][ni][h * 2 + 0] + rb;
                float vy = acc[mi][ni][h * 2 + 1] + rb;
                if (HAS_BIAS) { vx += bias[col]; vy += bias[col + 1]; }
                if (OUT_HALF) {
                    *reinterpret_cast<__half2*>(
                        (__half*)Cv + (size_t)row * N + col) =
                        __floats2half2_rn(vx, vy);
                } else {
                    float2 v2; v2.x = vx; v2.y = vy;
                    *reinterpret_cast<float2*>(
                        (float*)Cv + (size_t)row * N + col) = v2;
                }
            }
        }
    }
}

// kv = key @ W_v^T (grid (2,16)); block bx==0 also computes c = key·b_v
__global__ __launch_bounds__(128)
void kv_kernel(const float* __restrict__ key, const float* __restrict__ Wv,
               const float* __restrict__ bv,
               float* __restrict__ kv, float* __restrict__ c)
{
    const int bm = blockIdx.y * 64;
    gemm_core<true, false, false, false>(
        key, Wv, nullptr, nullptr, kv, 128, bm, blockIdx.x * 64);
    if (blockIdx.x == 0) {
        // c[i] = key[i]·b_v from the staged (tf32-rounded) A tile
        extern __shared__ uint32_t sm[];
        const int t = threadIdx.x;
        if (t < 64) {
            float s = 0.0f;
#pragma unroll 16
            for (int e = 0; e < 128; e++)
                s = fmaf(__uint_as_float(sm[t * 132 + e]), bv[e], s);
            c[bm + t] = s;
        }
    }
}

// Fused query projections: blocks x<16 -> off [1024x1024], x>=16 -> aw [1024x512]
__global__ __launch_bounds__(128)
void qproj_fused(const float* __restrict__ q,
                 const float* __restrict__ Woff, const float* __restrict__ boff,
                 const float* __restrict__ Wattn, const float* __restrict__ battn,
                 __half* __restrict__ off, __half* __restrict__ aw)
{
    const int bx = blockIdx.x;
    if (bx < 16)
        gemm_core<false, true, false, true>(
            q, Woff, boff, nullptr, off, 1024, blockIdx.y * 64, bx * 64);
    else
        gemm_core<false, true, false, true>(
            q, Wattn, battn, nullptr, aw, 512, blockIdx.y * 64, (bx - 16) * 64);
}

template <bool NT, bool HAS_BIAS, bool HAS_ROWB, bool OUT_HALF>
__global__ __launch_bounds__(128)
void gemm_tf32(const float* __restrict__ A, const float* __restrict__ B,
               const float* __restrict__ bias, const float* __restrict__ rowb,
               void* __restrict__ C, int N)
{
    gemm_core<NT, HAS_BIAS, HAS_ROWB, OUT_HALF>(
        A, B, bias, rowb, C, N, blockIdx.y * 64, blockIdx.x * 64);
}

// ---------------------------------------------------------------------------
// Output projection strip GEMM (R7 version):
//   out[1024,128] = M[1024,128] @ W_o[128,128] + b_o + query
// BM=16, BN=64, 128 threads (4 warps), warp tile 16x16. grid (2, 64).
// ---------------------------------------------------------------------------
#define OASZ (16 * 132)
#define OBSZ (128 * 72)
#define OUT_SMEM ((OASZ + OBSZ) * 4)

__global__ __launch_bounds__(128)
void out_proj_kernel(const float* __restrict__ M, const float* __restrict__ Wo,
                     const float* __restrict__ bo, const float* __restrict__ query,
                     float* __restrict__ out)
{
    extern __shared__ uint32_t sm[];
    uint32_t* As = sm;           // 16 x 132
    uint32_t* Bs = sm + OASZ;    // 128 x 72

    const int tid  = threadIdx.x;
    const int lane = tid & 31;
    const int warp = tid >> 5;
    const int grp  = lane >> 2;
    const int lk   = lane & 3;
    const int bm   = blockIdx.y * 16;
    const int bn   = blockIdx.x * 64;

#pragma unroll
    for (int l = 0; l < 4; l++) {
        int f = tid + l * 128;
        int m = f >> 5, k4 = f & 31;
        float4 v = *reinterpret_cast<const float4*>(M + (bm + m) * 128 + k4 * 4);
        uint32_t* d = &As[m * 132 + k4 * 4];
        d[0] = f2tf32(v.x); d[1] = f2tf32(v.y);
        d[2] = f2tf32(v.z); d[3] = f2tf32(v.w);
    }
#pragma unroll
    for (int l = 0; l < 16; l++) {
        int f = tid + l * 128;
        int k = f >> 4, n4 = f & 15;
        float4 v = *reinterpret_cast<const float4*>(Wo + k * 128 + bn + n4 * 4);
        uint32_t* d = &Bs[k * 72 + n4 * 4];
        d[0] = f2tf32(v.x); d[1] = f2tf32(v.y);
        d[2] = f2tf32(v.z); d[3] = f2tf32(v.w);
    }
    __syncthreads();

    float acc[2][4];
#pragma unroll
    for (int ni = 0; ni < 2; ni++)
#pragma unroll
        for (int r = 0; r < 4; r++) acc[ni][r] = 0.0f;

#pragma unroll
    for (int k8 = 0; k8 < 16; k8++) {
        const int kb = k8 * 8;
        uint32_t a[4], b[2][2];
        a[0] = As[grp * 132 + kb + lk];
        a[1] = As[(grp + 8) * 132 + kb + lk];
        a[2] = As[grp * 132 + kb + lk + 4];
        a[3] = As[(grp + 8) * 132 + kb + lk + 4];
#pragma unroll
        for (int ni = 0; ni < 2; ni++) {
            int nc = warp * 16 + ni * 8 + grp;
            b[ni][0] = Bs[(kb + lk) * 72 + nc];
            b[ni][1] = Bs[(kb + lk + 4) * 72 + nc];
        }
#pragma unroll
        for (int ni = 0; ni < 2; ni++)
            mma_tf32(acc[ni], a, b[ni]);
    }

#pragma unroll
    for (int ni = 0; ni < 2; ni++) {
#pragma unroll
        for (int h = 0; h < 2; h++) {
            int row = bm + grp + h * 8;
            int col = bn + warp * 16 + ni * 8 + 2 * lk;
            float2 r = *reinterpret_cast<const float2*>(query + row * 128 + col);
            float2 v;
            v.x = acc[ni][h * 2 + 0] + bo[col] + r.x;
            v.y = acc[ni][h * 2 + 1] + bo[col + 1] + r.y;
            *reinterpret_cast<float2*>(out + row * 128 + col) = v;
        }
    }
}

// ---------------------------------------------------------------------------
// Sampler (R7 version). One block per query q, 256 threads: (half,d).
// ---------------------------------------------------------------------------
__global__ __launch_bounds__(256)
void sample_kernel(const __half* __restrict__ S,
                   const __half* __restrict__ off,
                   const __half* __restrict__ aw,
                   const float* __restrict__ ref3d,
                   float* __restrict__ M)
{
    __shared__ __half srow[NV];
    __shared__ float red[256];
    const int q = blockIdx.x;
    const int t = threadIdx.x;
    const int hf = t >> 7;
    const int d = t & 127;

    reinterpret_cast<uint2*>(srow)[t] =
        reinterpret_cast<const uint2*>(S + (size_t)q * NV)[t];

    const __half2* awp = reinterpret_cast<const __half2*>(aw + q * 512 + d * 4);
    float2 a01 = __half22float2(awp[0]);
    float2 a23 = __half22float2(awp[1]);
    float mx = fmaxf(fmaxf(a01.x, a01.y), fmaxf(a23.x, a23.y));
    float e0 = __expf(a01.x - mx), e1 = __expf(a01.y - mx);
    float e2 = __expf(a23.x - mx), e3 = __expf(a23.y - mx);
    float inv = 1.0f / (e0 + e1 + e2 + e3);
    float wp[2] = { (hf ? e2 : e0) * inv, (hf ? e3 : e1) * inv };

    const int qe = q * ND + d;
    const float2 rf = *reinterpret_cast<const float2*>(ref3d + qe * 2);
    const float rx = rf.x * 32.0f - 0.5f;
    const float ry = rf.y * 32.0f - 0.5f;

    const __half2* op = reinterpret_cast<const __half2*>(
        off + q * 1024 + d * 8 + hf * 4);
    float2 p0 = __half22float2(op[0]);
    float2 p1 = __half22float2(op[1]);
    float ox[2] = { p0.x, p1.x };
    float oy[2] = { p0.y, p1.y };

    __syncthreads();

    float acc = 0.0f;
#pragma unroll
    for (int p = 0; p < 2; p++) {
        float x = rx + ox[p];
        float y = ry + oy[p];
        float xf = floorf(x), yf = floorf(y);
        int ix0 = (int)xf, iy0 = (int)yf;
        float wx1 = x - xf, wy1 = y - yf;
        float wx0 = 1.0f - wx1, wy0 = 1.0f - wy1;

        float s = 0.0f;
#pragma unroll
        for (int cc = 0; cc < 4; cc++) {
            int cx = ix0 + (cc & 1);
            int cy = iy0 + (cc >> 1);
            float wt = ((cc & 1) ? wx1 : wx0) * ((cc >> 1) ? wy1 : wy0);
            if (cx >= 0 && cx < 32 && cy >= 0 && cy < 32)
                s += wt * __half2float(srow[cy * 32 + cx]);
        }
        acc += wp[p] * s;
    }
    red[t] = acc;
    __syncthreads();
    if (t < 128)
        M[qe] = (red[t] + red[t + 128]) * (1.0f / 128.0f);
}

// ---------------------------------------------------------------------------
extern "C" void kernel_launch(void* const* d_in, const int* in_sizes, int n_in,
                              void* d_out, int out_size)
{
    const float* query  = (const float*)d_in[0];
    const float* key    = (const float*)d_in[1];
    const float* value  = (const float*)d_in[2];
    const float* ref3d  = (const float*)d_in[3];
    // d_in[4] spatial_shapes: fixed [[32,32]], hardcoded
    const float* W_off  = (const float*)d_in[5];
    const float* b_off  = (const float*)d_in[6];
    const float* W_attn = (const float*)d_in[7];
    const float* b_attn = (const float*)d_in[8];
    const float* W_v    = (const float*)d_in[9];
    const float* b_v    = (const float*)d_in[10];
    const float* W_o    = (const float*)d_in[11];
    const float* b_o    = (const float*)d_in[12];
    float* out = (float*)d_out;

    float *p_kv, *p_c, *p_M;
    __half *p_S, *p_off, *p_aw;
    cudaGetSymbolAddress((void**)&p_kv,  g_kv);
    cudaGetSymbolAddress((void**)&p_c,   g_c);
    cudaGetSymbolAddress((void**)&p_S,   g_S);
    cudaGetSymbolAddress((void**)&p_off, g_off);
    cudaGetSymbolAddress((void**)&p_aw,  g_aw);
    cudaGetSymbolAddress((void**)&p_M,   g_M);

    cudaFuncSetAttribute(kv_kernel,
                         cudaFuncAttributeMaxDynamicSharedMemorySize, GEMM_SMEM);
    cudaFuncSetAttribute(qproj_fused,
                         cudaFuncAttributeMaxDynamicSharedMemorySize, GEMM_SMEM);
    cudaFuncSetAttribute(gemm_tf32<true, false, true, true>,
                         cudaFuncAttributeMaxDynamicSharedMemorySize, GEMM_SMEM);
    cudaFuncSetAttribute(out_proj_kernel,
                         cudaFuncAttributeMaxDynamicSharedMemorySize, OUT_SMEM);

    // Fork capture: off/aw (depends only on query) runs on side stream,
    // fully concurrent with the kv -> S chain on the main stream.
    static cudaStream_t s1 = nullptr;
    static cudaEvent_t evFork = nullptr, evJoin = nullptr;
    if (s1 == nullptr) {
        cudaStreamCreateWithFlags(&s1, cudaStreamNonBlocking);
        cudaEventCreateWithFlags(&evFork, cudaEventDisableTiming);
        cudaEventCreateWithFlags(&evJoin, cudaEventDisableTiming);
    }

    cudaEventRecord(evFork, (cudaStream_t)0);
    cudaStreamWaitEvent(s1, evFork, 0);

    // side stream: off = q @ W_off + b_off ; aw = q @ W_attn + b_attn
    qproj_fused<<<dim3(24, 16), 128, GEMM_SMEM, s1>>>(
        query, W_off, b_off, W_attn, b_attn, p_off, p_aw);
    cudaEventRecord(evJoin, s1);

    // main stream: kv (+c) -> S
    kv_kernel<<<dim3(2, 16), 128, GEMM_SMEM>>>(key, W_v, b_v, p_kv, p_c);
    gemm_tf32<true, false, true, true><<<dim3(16, 16), 128, GEMM_SMEM>>>(
        p_kv, value, nullptr, p_c, p_S, 1024);

    cudaStreamWaitEvent((cudaStream_t)0, evJoin, 0);

    // sampler -> M, then out-projection
    sample_kernel<<<1024, 256>>>(p_S, p_off, p_aw, ref3d, p_M);
    out_proj_kernel<<<dim3(2, 64), 128, OUT_SMEM>>>(p_M, W_o, b_o, query, out);
}

// round 11
// speedup vs baseline: 1.1827x; 1.1799x over previous
#include <cuda_runtime.h>
#include <cuda_fp16.h>
#include <cstdint>

// Problem constants (fixed by reference):
//   bsv=1, nq=nv=1024, E=128, NUM_DEPTH=128, NUM_POINTS=4, H=W=32, cams=heads=levels=1
// Inputs (metadata order):
//   0 query[1024,128] 1 key[1024,128] 2 value[1024,128] 3 ref_3d[131072,2]
//   4 spatial_shapes[1,2] 5 W_off[128,1024] 6 b_off[1024] 7 W_attn[128,512]
//   8 b_attn[512] 9 W_v[128,128] 10 b_v[128] 11 W_o[128,128] 12 b_o[128]
// Output: float32 [1024,128]
//
// Algebra: S = key @ (value@W_v + b_v)^T = (key@W_v^T) @ value^T + c,
//          c[i] = key[i]·b_v.
// R7 baseline (23.0us) + Programmatic Dependent Launch: dependent kernels
// stage their INDEPENDENT operands before griddepcontrol.wait, overlapping
// each kernel's epilogue/tail with the successor's prologue.

#define NQ 1024
#define NV 1024
#define ND 128

// Scratch (allocation-free: __device__ globals)
__device__ float  g_kv[NQ * 128];      // key @ W_v^T                 (fp32)
__device__ float  g_c[NQ];             // key @ b_v  (row bias for S) (fp32)
__device__ __half g_S[NQ * NV];        // kv @ value^T + c            (fp16)
__device__ __half g_off[NQ * 1024];    // query @ W_off + b_off       (fp16)
__device__ __half g_aw[NQ * 512];      // query @ W_attn + b_attn     (fp16)
__device__ float  g_M[NQ * ND];        // sampled, pre-output-proj    (fp32)

// ---------------------------------------------------------------------------
__device__ __forceinline__ uint32_t f2tf32(float f) {
    uint32_t u;
    asm("cvt.rna.tf32.f32 %0, %1;" : "=r"(u) : "f"(f));
    return u;
}

__device__ __forceinline__ void mma_tf32(float c[4], const uint32_t a[4],
                                         const uint32_t b[2]) {
    asm volatile(
        "mma.sync.aligned.m16n8k8.row.col.f32.tf32.tf32.f32 "
        "{%0,%1,%2,%3}, {%4,%5,%6,%7}, {%8,%9}, {%0,%1,%2,%3};"
        : "+f"(c[0]), "+f"(c[1]), "+f"(c[2]), "+f"(c[3])
        : "r"(a[0]), "r"(a[1]), "r"(a[2]), "r"(a[3]), "r"(b[0]), "r"(b[1]));
}

// PDL intrinsics
__device__ __forceinline__ void pdl_trigger() {
    asm volatile("griddepcontrol.launch_dependents;");
}
__device__ __forceinline__ void pdl_wait() {
    asm volatile("griddepcontrol.wait;" ::: "memory");
}

// ---------------------------------------------------------------------------
// tf32 GEMM core, FULL-K staging (K=128), tf32 cvt at stage time (R7-proven).
// BM=BN=64, 128 threads (4 warps, 2x2 warp grid, 32x32 warp tiles).
// NT: B is [N,128] (compute A @ B^T); else B is [128,N] row-major.
// ---------------------------------------------------------------------------
#define ASZ (64 * 132)
#define BSZ (128 * 72)
#define GEMM_SMEM ((ASZ + BSZ) * 4)

// ---- staging helpers --------------------------------------------------------
__device__ __forceinline__ void stage_A64(const float* __restrict__ A,
                                          int bm, uint32_t* As) {
    const int tid = threadIdx.x;
#pragma unroll
    for (int l = 0; l < 16; l++) {
        int f = tid + l * 128;
        int m = f >> 5, k4 = f & 31;
        float4 v = *reinterpret_cast<const float4*>(A + (bm + m) * 128 + k4 * 4);
        uint32_t* d = &As[m * 132 + k4 * 4];
        d[0] = f2tf32(v.x); d[1] = f2tf32(v.y);
        d[2] = f2tf32(v.z); d[3] = f2tf32(v.w);
    }
}
__device__ __forceinline__ void stage_B_NT(const float* __restrict__ B,
                                           int bn, uint32_t* Bs) {
    const int tid = threadIdx.x;
#pragma unroll
    for (int l = 0; l < 16; l++) {
        int f = tid + l * 128;
        int n = f >> 5, k4 = f & 31;
        float4 v = *reinterpret_cast<const float4*>(B + (bn + n) * 128 + k4 * 4);
        uint32_t* d = &Bs[n * 132 + k4 * 4];
        d[0] = f2tf32(v.x); d[1] = f2tf32(v.y);
        d[2] = f2tf32(v.z); d[3] = f2tf32(v.w);
    }
}
__device__ __forceinline__ void stage_B_NN(const float* __restrict__ B,
                                           int N, int bn, uint32_t* Bs) {
    const int tid = threadIdx.x;
#pragma unroll
    for (int l = 0; l < 16; l++) {
        int f = tid + l * 128;
        int k = f >> 4, n4 = f & 15;
        float4 v = *reinterpret_cast<const float4*>(B + k * N + bn + n4 * 4);
        uint32_t* d = &Bs[k * 72 + n4 * 4];
        d[0] = f2tf32(v.x); d[1] = f2tf32(v.y);
        d[2] = f2tf32(v.z); d[3] = f2tf32(v.w);
    }
}

// ---- 64x64 mainloop + epilogue ---------------------------------------------
template <bool NT, bool HAS_BIAS, bool HAS_ROWB, bool OUT_HALF>
__device__ __forceinline__ void mma_and_store(
    const uint32_t* As, const uint32_t* Bs,
    const float* __restrict__ bias, const float* __restrict__ rowb,
    void* __restrict__ Cv, int N, int bm, int bn, bool trigger)
{
    const int tid  = threadIdx.x;
    const int lane = tid & 31;
    const int warp = tid >> 5;
    const int wm   = warp >> 1;
    const int wn   = warp & 1;
    const int grp  = lane >> 2;
    const int lk   = lane & 3;

    float acc[2][4][4];
#pragma unroll
    for (int mi = 0; mi < 2; mi++)
#pragma unroll
        for (int ni = 0; ni < 4; ni++)
#pragma unroll
            for (int r = 0; r < 4; r++) acc[mi][ni][r] = 0.0f;

#pragma unroll
    for (int k8 = 0; k8 < 16; k8++) {
        const int kb = k8 * 8;
        uint32_t a[2][4], b[4][2];
#pragma unroll
        for (int mi = 0; mi < 2; mi++) {
            int mr = wm * 32 + mi * 16 + grp;
            a[mi][0] = As[mr * 132 + kb + lk];
            a[mi][1] = As[(mr + 8) * 132 + kb + lk];
            a[mi][2] = As[mr * 132 + kb + lk + 4];
            a[mi][3] = As[(mr + 8) * 132 + kb + lk + 4];
        }
#pragma unroll
        for (int ni = 0; ni < 4; ni++) {
            int nc = wn * 32 + ni * 8 + grp;
            if (NT) {
                b[ni][0] = Bs[nc * 132 + kb + lk];
                b[ni][1] = Bs[nc * 132 + kb + lk + 4];
            } else {
                b[ni][0] = Bs[(kb + lk) * 72 + nc];
                b[ni][1] = Bs[(kb + lk + 4) * 72 + nc];
            }
        }
#pragma unroll
        for (int mi = 0; mi < 2; mi++)
#pragma unroll
            for (int ni = 0; ni < 4; ni++)
                mma_tf32(acc[mi][ni], a[mi], b[ni]);
    }

    if (trigger) pdl_trigger();   // dependents may begin their prologues

#pragma unroll
    for (int mi = 0; mi < 2; mi++) {
#pragma unroll
        for (int h = 0; h < 2; h++) {
            int row = bm + wm * 32 + mi * 16 + grp + h * 8;
            float rb = HAS_ROWB ? rowb[row] : 0.0f;
#pragma unroll
            for (int ni = 0; ni < 4; ni++) {
                int col = bn + wn * 32 + ni * 8 + 2 * lk;
                float vx = acc[mi][ni][h * 2 + 0] + rb;
                float vy = acc[mi][ni][h * 2 + 1] + rb;
                if (HAS_BIAS) { vx += bias[col]; vy += bias[col + 1]; }
                if (OUT_HALF) {
                    *reinterpret_cast<__half2*>(
                        (__half*)Cv + (size_t)row * N + col) =
                        __floats2half2_rn(vx, vy);
                } else {
                    float2 v2; v2.x = vx; v2.y = vy;
                    *reinterpret_cast<float2*>(
                        (float*)Cv + (size_t)row * N + col) = v2;
                }
            }
        }
    }
}

// ---------------------------------------------------------------------------
// Stage 1 (single launch): grid (26, 16)
//   bx 0..15  : off = query @ W_off + b_off        [1024x1024] fp16
//   bx 16..23 : aw  = query @ W_attn + b_attn      [1024x512]  fp16
//   bx 24..25 : kv  = key @ W_v^T                  [1024x128]  fp32
//               (bx==24 also computes c[i] = key[i]·b_v from staged A tile)
// All inputs are external -> no pdl_wait needed; triggers for the S kernel.
// ---------------------------------------------------------------------------
__global__ __launch_bounds__(128)
void stage1_kernel(const float* __restrict__ query,
                   const float* __restrict__ key,
                   const float* __restrict__ Woff, const float* __restrict__ boff,
                   const float* __restrict__ Wattn, const float* __restrict__ battn,
                   const float* __restrict__ Wv, const float* __restrict__ bv,
                   __half* __restrict__ off, __half* __restrict__ aw,
                   float* __restrict__ kv, float* __restrict__ c)
{
    extern __shared__ uint32_t sm[];
    uint32_t* As = sm;
    uint32_t* Bs = sm + ASZ;
    const int bx = blockIdx.x;
    const int bm = blockIdx.y * 64;

    if (bx < 16) {
        stage_A64(query, bm, As);
        stage_B_NN(Woff, 1024, bx * 64, Bs);
        __syncthreads();
        mma_and_store<false, true, false, true>(
            As, Bs, boff, nullptr, off, 1024, bm, bx * 64, true);
    } else if (bx < 24) {
        stage_A64(query, bm, As);
        stage_B_NN(Wattn, 512, (bx - 16) * 64, Bs);
        __syncthreads();
        mma_and_store<false, true, false, true>(
            As, Bs, battn, nullptr, aw, 512, bm, (bx - 16) * 64, true);
    } else {
        stage_A64(key, bm, As);
        stage_B_NT(Wv, (bx - 24) * 64, Bs);
        __syncthreads();
        mma_and_store<true, false, false, false>(
            As, Bs, nullptr, nullptr, kv, 128, bm, (bx - 24) * 64, true);
        if (bx == 24) {
            const int t = threadIdx.x;
            if (t < 64) {
                float s = 0.0f;
#pragma unroll 16
                for (int e = 0; e < 128; e++)
                    s = fmaf(__uint_as_float(As[t * 132 + e]), bv[e], s);
                c[bm + t] = s;
            }
        }
    }
}

// ---------------------------------------------------------------------------
// S = kv @ value^T + c[row]  (PDL consumer: stages value BEFORE the wait)
// ---------------------------------------------------------------------------
__global__ __launch_bounds__(128)
void s_gemm_kernel(const float* __restrict__ kv, const float* __restrict__ value,
                   const float* __restrict__ c, __half* __restrict__ S)
{
    extern __shared__ uint32_t sm[];
    uint32_t* As = sm;
    uint32_t* Bs = sm + ASZ;
    const int bm = blockIdx.y * 64;
    const int bn = blockIdx.x * 64;

    stage_B_NT(value, bn, Bs);   // independent input: overlap with stage1 tail
    pdl_wait();                  // kv, c now valid
    stage_A64(kv, bm, As);
    __syncthreads();
    mma_and_store<true, false, true, true>(
        As, Bs, nullptr, c, S, 1024, bm, bn, true);
}

// ---------------------------------------------------------------------------
// Sampler (R7 version) + PDL. One block per query q, 256 threads: (half,d).
// ---------------------------------------------------------------------------
__global__ __launch_bounds__(256)
void sample_kernel(const __half* __restrict__ S,
                   const __half* __restrict__ off,
                   const __half* __restrict__ aw,
                   const float* __restrict__ ref3d,
                   float* __restrict__ M)
{
    __shared__ __half srow[NV];
    __shared__ float red[256];
    const int q = blockIdx.x;
    const int t = threadIdx.x;
    const int hf = t >> 7;
    const int d = t & 127;

    // ref3d is an external input: load before the wait
    const int qe = q * ND + d;
    const float2 rf = *reinterpret_cast<const float2*>(ref3d + qe * 2);
    const float rx = rf.x * 32.0f - 0.5f;
    const float ry = rf.y * 32.0f - 0.5f;

    pdl_wait();                  // S, off, aw now valid

    reinterpret_cast<uint2*>(srow)[t] =
        reinterpret_cast<const uint2*>(S + (size_t)q * NV)[t];

    const __half2* awp = reinterpret_cast<const __half2*>(aw + q * 512 + d * 4);
    float2 a01 = __half22float2(awp[0]);
    float2 a23 = __half22float2(awp[1]);
    float mx = fmaxf(fmaxf(a01.x, a01.y), fmaxf(a23.x, a23.y));
    float e0 = __expf(a01.x - mx), e1 = __expf(a01.y - mx);
    float e2 = __expf(a23.x - mx), e3 = __expf(a23.y - mx);
    float inv = 1.0f / (e0 + e1 + e2 + e3);
    float wp[2] = { (hf ? e2 : e0) * inv, (hf ? e3 : e1) * inv };

    const __half2* op = reinterpret_cast<const __half2*>(
        off + q * 1024 + d * 8 + hf * 4);
    float2 p0 = __half22float2(op[0]);
    float2 p1 = __half22float2(op[1]);
    float ox[2] = { p0.x, p1.x };
    float oy[2] = { p0.y, p1.y };

    __syncthreads();

    float acc = 0.0f;
#pragma unroll
    for (int p = 0; p < 2; p++) {
        float x = rx + ox[p];
        float y = ry + oy[p];
        float xf = floorf(x), yf = floorf(y);
        int ix0 = (int)xf, iy0 = (int)yf;
        float wx1 = x - xf, wy1 = y - yf;
        float wx0 = 1.0f - wx1, wy0 = 1.0f - wy1;

        float s = 0.0f;
#pragma unroll
        for (int cc = 0; cc < 4; cc++) {
            int cx = ix0 + (cc & 1);
            int cy = iy0 + (cc >> 1);
            float wt = ((cc & 1) ? wx1 : wx0) * ((cc >> 1) ? wy1 : wy0);
            if (cx >= 0 && cx < 32 && cy >= 0 && cy < 32)
                s += wt * __half2float(srow[cy * 32 + cx]);
        }
        acc += wp[p] * s;
    }
    red[t] = acc;
    pdl_trigger();
    __syncthreads();
    if (t < 128)
        M[qe] = (red[t] + red[t + 128]) * (1.0f / 128.0f);
}

// ---------------------------------------------------------------------------
// Output projection strip GEMM (R7 version) + PDL:
//   out[1024,128] = M[1024,128] @ W_o[128,128] + b_o + query
// BM=16, BN=64, grid (2, 64). Stages W_o (64KB, independent) BEFORE the wait.
// ---------------------------------------------------------------------------
#define OASZ (16 * 132)
#define OBSZ (128 * 72)
#define OUT_SMEM ((OASZ + OBSZ) * 4)

__global__ __launch_bounds__(128)
void out_proj_kernel(const float* __restrict__ M, const float* __restrict__ Wo,
                     const float* __restrict__ bo, const float* __restrict__ query,
                     float* __restrict__ out)
{
    extern __shared__ uint32_t sm[];
    uint32_t* As = sm;           // 16 x 132
    uint32_t* Bs = sm + OASZ;    // 128 x 72

    const int tid  = threadIdx.x;
    const int lane = tid & 31;
    const int warp = tid >> 5;
    const int grp  = lane >> 2;
    const int lk   = lane & 3;
    const int bm   = blockIdx.y * 16;
    const int bn   = blockIdx.x * 64;

    // W_o is an external input: stage before the wait (the dominant cost)
#pragma unroll
    for (int l = 0; l < 16; l++) {
        int f = tid + l * 128;
        int k = f >> 4, n4 = f & 15;
        float4 v = *reinterpret_cast<const float4*>(Wo + k * 128 + bn + n4 * 4);
        uint32_t* d = &Bs[k * 72 + n4 * 4];
        d[0] = f2tf32(v.x); d[1] = f2tf32(v.y);
        d[2] = f2tf32(v.z); d[3] = f2tf32(v.w);
    }
    pdl_wait();                  // M now valid
#pragma unroll
    for (int l = 0; l < 4; l++) {
        int f = tid + l * 128;
        int m = f >> 5, k4 = f & 31;
        float4 v = *reinterpret_cast<const float4*>(M + (bm + m) * 128 + k4 * 4);
        uint32_t* d = &As[m * 132 + k4 * 4];
        d[0] = f2tf32(v.x); d[1] = f2tf32(v.y);
        d[2] = f2tf32(v.z); d[3] = f2tf32(v.w);
    }
    __syncthreads();

    float acc[2][4];
#pragma unroll
    for (int ni = 0; ni < 2; ni++)
#pragma unroll
        for (int r = 0; r < 4; r++) acc[ni][r] = 0.0f;

#pragma unroll
    for (int k8 = 0; k8 < 16; k8++) {
        const int kb = k8 * 8;
        uint32_t a[4], b[2][2];
        a[0] = As[grp * 132 + kb + lk];
        a[1] = As[(grp + 8) * 132 + kb + lk];
        a[2] = As[grp * 132 + kb + lk + 4];
        a[3] = As[(grp + 8) * 132 + kb + lk + 4];
#pragma unroll
        for (int ni = 0; ni < 2; ni++) {
            int nc = warp * 16 + ni * 8 + grp;
            b[ni][0] = Bs[(kb + lk) * 72 + nc];
            b[ni][1] = Bs[(kb + lk + 4) * 72 + nc];
        }
#pragma unroll
        for (int ni = 0; ni < 2; ni++)
            mma_tf32(acc[ni], a, b[ni]);
    }

#pragma unroll
    for (int ni = 0; ni < 2; ni++) {
#pragma unroll
        for (int h = 0; h < 2; h++) {
            int row = bm + grp + h * 8;
            int col = bn + warp * 16 + ni * 8 + 2 * lk;
            float2 r = *reinterpret_cast<const float2*>(query + row * 128 + col);
            float2 v;
            v.x = acc[ni][h * 2 + 0] + bo[col] + r.x;
            v.y = acc[ni][h * 2 + 1] + bo[col + 1] + r.y;
            *reinterpret_cast<float2*>(out + row * 128 + col) = v;
        }
    }
}

// ---------------------------------------------------------------------------
template <typename... Args>
static inline void launch_pdl(void (*kern)(Args...), dim3 grid, dim3 block,
                              size_t smem, Args... args)
{
    cudaLaunchConfig_t cfg = {};
    cfg.gridDim = grid;
    cfg.blockDim = block;
    cfg.dynamicSmemBytes = smem;
    cfg.stream = (cudaStream_t)0;
    cudaLaunchAttribute attr[1];
    attr[0].id = cudaLaunchAttributeProgrammaticStreamSerialization;
    attr[0].val.programmaticStreamSerializationAllowed = 1;
    cfg.attrs = attr;
    cfg.numAttrs = 1;
    cudaLaunchKernelEx(&cfg, kern, args...);
}

extern "C" void kernel_launch(void* const* d_in, const int* in_sizes, int n_in,
                              void* d_out, int out_size)
{
    const float* query  = (const float*)d_in[0];
    const float* key    = (const float*)d_in[1];
    const float* value  = (const float*)d_in[2];
    const float* ref3d  = (const float*)d_in[3];
    // d_in[4] spatial_shapes: fixed [[32,32]], hardcoded
    const float* W_off  = (const float*)d_in[5];
    const float* b_off  = (const float*)d_in[6];
    const float* W_attn = (const float*)d_in[7];
    const float* b_attn = (const float*)d_in[8];
    const float* W_v    = (const float*)d_in[9];
    const float* b_v    = (const float*)d_in[10];
    const float* W_o    = (const float*)d_in[11];
    const float* b_o    = (const float*)d_in[12];
    float* out = (float*)d_out;

    float *p_kv, *p_c, *p_M;
    __half *p_S, *p_off, *p_aw;
    cudaGetSymbolAddress((void**)&p_kv,  g_kv);
    cudaGetSymbolAddress((void**)&p_c,   g_c);
    cudaGetSymbolAddress((void**)&p_S,   g_S);
    cudaGetSymbolAddress((void**)&p_off, g_off);
    cudaGetSymbolAddress((void**)&p_aw,  g_aw);
    cudaGetSymbolAddress((void**)&p_M,   g_M);

    cudaFuncSetAttribute(stage1_kernel,
                         cudaFuncAttributeMaxDynamicSharedMemorySize, GEMM_SMEM);
    cudaFuncSetAttribute(s_gemm_kernel,
                         cudaFuncAttributeMaxDynamicSharedMemorySize, GEMM_SMEM);
    cudaFuncSetAttribute(out_proj_kernel,
                         cudaFuncAttributeMaxDynamicSharedMemorySize, OUT_SMEM);

    // 1. stage1: off/aw projections + kv + c (one launch, first in chain)
    stage1_kernel<<<dim3(26, 16), 128, GEMM_SMEM>>>(
        query, key, W_off, b_off, W_attn, b_attn, W_v, b_v,
        p_off, p_aw, p_kv, p_c);

    // 2. S = kv @ value^T + c[row]   (PDL: stages value during stage1 tail)
    launch_pdl(s_gemm_kernel, dim3(16, 16), dim3(128), (size_t)GEMM_SMEM,
               (const float*)p_kv, value, (const float*)p_c, p_S);

    // 3. sampler -> M                (PDL: dispatch + ref3d before wait)
    launch_pdl(sample_kernel, dim3(1024), dim3(256), (size_t)0,
               (const __half*)p_S, (const __half*)p_off, (const __half*)p_aw,
               ref3d, p_M);

    // 4. out = M @ W_o + b_o + query (PDL: stages W_o during sampler)
    launch_pdl(out_proj_kernel, dim3(2, 64), dim3(128), (size_t)OUT_SMEM,
               (const float*)p_M, W_o, b_o, query, out);
}